// round 4
// baseline (speedup 1.0000x reference)
#include <cuda_runtime.h>
#include <math.h>
#include <stdint.h>

// Problem shape (fixed by reference setup_inputs)
#define BB 16
#define CC 8
#define HH 512
#define WW 512
#define NT 64
#define HWSZ (HH * WW)            // 262144
#define CHUNK_FLOATS 8192         // 32KB per block chunk
#define CHUNK_BYTES  (CHUNK_FLOATS * 4)

#define SP_BLOCKS 512             // 512 chunks * 8192 floats = 16*262144 (channel 0)
#define NBLOCKS   (SP_BLOCKS + 1) // block 0 = targets
#define NTHREADS  512
#define F4_PER_THREAD 4           // 512 thr * 4 float4 * 4 = 8192 floats

// ---- accumulators (device globals: zero-initialized; finalize resets them) ----
__device__ double       g_cls_sum;
__device__ float        g_xmask_sum;
__device__ float        g_reg_sum;
__device__ int          g_num;
__device__ unsigned int g_done;

__device__ __forceinline__ uint32_t smem_u32(const void* p) {
    return (uint32_t)__cvta_generic_to_shared(p);
}

__device__ __forceinline__ float softplus_fast(float x) {
    float t = __expf(-fabsf(x));                 // MUFU ex2
    return fmaxf(x, 0.0f) + __logf(1.0f + t);    // MUFU lg2
}
__device__ __forceinline__ float sp4(float4 v) {
    return softplus_fast(v.x) + softplus_fast(v.y)
         + softplus_fast(v.z) + softplus_fast(v.w);
}

__global__ __launch_bounds__(NTHREADS)
void dl_fused_k(const float* __restrict__ preds,
                const float* __restrict__ tg,
                float* __restrict__ out, int out_size) {
    const int tid = threadIdx.x;

    __shared__ __align__(128) union {
        float4 data[CHUNK_FLOATS / 4];   // 32KB streaming buffer (SP blocks)
        int    cell[BB * NT];            // dedupe table (block 0)
    } sm;
    __shared__ __align__(8) unsigned long long s_mbar;

    if (blockIdx.x != 0) {
        // ---------- bulk-async copy of this block's channel-0 chunk ----------
        const int chunk = blockIdx.x - 1;              // 0..511
        const int b     = chunk >> 5;                  // 32 chunks per batch
        const float* src = preds + (size_t)b * (CC * HWSZ)
                                 + (size_t)(chunk & 31) * CHUNK_FLOATS;
        const uint32_t mbar = smem_u32(&s_mbar);
        const uint32_t dst  = smem_u32(sm.data);

        if (tid == 0) {
            asm volatile("mbarrier.init.shared.b64 [%0], %1;"
                         :: "r"(mbar), "r"(1) : "memory");
        }
        __syncthreads();
        if (tid == 0) {
            asm volatile("mbarrier.arrive.expect_tx.shared.b64 _, [%0], %1;"
                         :: "r"(mbar), "r"(CHUNK_BYTES) : "memory");
            asm volatile(
                "cp.async.bulk.shared::cta.global.mbarrier::complete_tx::bytes"
                " [%0], [%1], %2, [%3];"
                :: "r"(dst), "l"(src), "r"(CHUNK_BYTES), "r"(mbar) : "memory");
        }
        // wait (parity 0) with acquire so subsequent smem reads are ordered
        {
            uint32_t done_;
            asm volatile(
                "{\n\t.reg .pred p;\n\t"
                "mbarrier.try_wait.parity.acquire.cta.shared::cta.b64 p, [%1], %2;\n\t"
                "selp.b32 %0, 1, 0, p;\n\t}"
                : "=r"(done_) : "r"(mbar), "r"(0) : "memory");
            if (!done_) {
                asm volatile(
                    "{\n\t.reg .pred P1;\n\t"
                    "WAIT_LOOP_%=:\n\t"
                    "mbarrier.try_wait.parity.acquire.cta.shared::cta.b64 P1, [%0], %1, 0x989680;\n\t"
                    "@P1 bra.uni WAIT_DONE_%=;\n\t"
                    "bra.uni WAIT_LOOP_%=;\n\t"
                    "WAIT_DONE_%=:\n\t}"
                    :: "r"(mbar), "r"(0) : "memory");
            }
        }

        // ---------- softplus from shared memory ----------
        float s = 0.0f;
        #pragma unroll
        for (int k = 0; k < F4_PER_THREAD; k++)
            s += sp4(sm.data[tid + k * NTHREADS]);

        #pragma unroll
        for (int o = 16; o > 0; o >>= 1) s += __shfl_down_sync(0xffffffffu, s, o);
        __shared__ float sh[16];
        int lane = tid & 31, w = tid >> 5;
        if (lane == 0) sh[w] = s;
        __syncthreads();
        if (w == 0) {
            s = (lane < (NTHREADS / 32)) ? sh[lane] : 0.0f;
            #pragma unroll
            for (int o = 8; o > 0; o >>= 1) s += __shfl_down_sync(0xffffffffu, s, o);
            if (lane == 0) atomicAdd(&g_cls_sum, (double)s);
        }
    } else {
        // ---------- targets block: dedupe + gather (512 threads x 2 targets) ----------
        const float sc = 512.0f / 80.0f;   // f32(6.4), matches JAX scalar rounding
        int   gx_[2], gy_[2], cell_[2];
        float tv_[2][7];
        #pragma unroll
        for (int r = 0; r < 2; r++) {
            int t = tid + r * NTHREADS;
            int b = t >> 6;
            const float* tp = tg + (size_t)t * 7;
            #pragma unroll
            for (int c = 0; c < 7; c++) tv_[r][c] = tp[c];
            gx_[r] = (int)fminf(fmaxf(tv_[r][0] * sc, 0.0f), 511.0f);
            gy_[r] = (int)fminf(fmaxf(tv_[r][1] * sc, 0.0f), 511.0f);
            cell_[r] = (b << 18) | (gy_[r] << 9) | gx_[r];
            sm.cell[t] = cell_[r];
        }
        __syncthreads();

        float xsum = 0.0f, rsum = 0.0f;
        int   nsum = 0;
        #pragma unroll
        for (int r = 0; r < 2; r++) {
            int t = tid + r * NTHREADS;
            int b = t >> 6;
            bool win = true;
            int end = (b << 6) + NT;
            for (int j = t + 1; j < end; j++)
                if (sm.cell[j] == cell_[r]) { win = false; break; }
            if (win) {
                size_t base = (size_t)b * CC * HWSZ + (size_t)gy_[r] * WW + gx_[r];
                xsum += preds[base];
                #pragma unroll
                for (int c = 0; c < 7; c++) {
                    float d  = preds[base + (size_t)(c + 1) * HWSZ] - tv_[r][c];
                    float ad = fabsf(d);
                    rsum += (ad < 1.0f) ? 0.5f * d * d : ad - 0.5f;
                }
                nsum += 1;
            }
        }
        if (xsum != 0.0f || nsum) atomicAdd(&g_xmask_sum, xsum);
        if (rsum != 0.0f || nsum) atomicAdd(&g_reg_sum, rsum);
        if (nsum)                 atomicAdd(&g_num, nsum);
    }

    // ---------- last-block finalize ----------
    __threadfence();
    __shared__ bool s_last;
    if (tid == 0)
        s_last = (atomicAdd(&g_done, 1u) == (unsigned)(NBLOCKS - 1));
    __syncthreads();
    if (s_last && tid == 0) {
        float num = (float)g_num;
        float cls = (float)((g_cls_sum - (double)g_xmask_sum) /
                            (double)((size_t)BB * HWSZ));
        float reg = (num > 0.0f) ? (g_reg_sum / (num + 1e-6f)) : 0.0f;
        out[0] = cls + 2.0f * reg;
        if (out_size > 1) out[1] = num;
        g_cls_sum   = 0.0;
        g_xmask_sum = 0.0f;
        g_reg_sum   = 0.0f;
        g_num       = 0;
        __threadfence();
        g_done      = 0u;
    }
}

extern "C" void kernel_launch(void* const* d_in, const int* in_sizes, int n_in,
                              void* d_out, int out_size) {
    const float* preds   = (const float*)d_in[0];   // (16,8,512,512) f32
    const float* targets = (const float*)d_in[1];   // (16,64,7)     f32
    float* out = (float*)d_out;

    dl_fused_k<<<NBLOCKS, NTHREADS>>>(preds, targets, out, out_size);

    (void)in_sizes; (void)n_in;
}